// round 2
// baseline (speedup 1.0000x reference)
#include <cuda_runtime.h>

#define CDIM 256
#define KCB  512

static const int N_ENC0  = 8*256*64*64;        // 8388608
static const int OFF_Z   = N_ENC0;
static const int OFF_STE = N_ENC0 + 8*2*64*64; // + 65536

// ---- scratch (device globals; no allocation anywhere) ----
__device__ float g_img1[8*3*128*128];
__device__ float g_img2[8*3*64*64];
__device__ float g_enc0[8*64*64*256];   // NHWC scale0
__device__ float g_enc1[8*32*32*256];   // NHWC scale1
__device__ float g_enc2[8*16*16*256];   // NHWC scale2
__device__ float g_cbsq[2*KCB];
__device__ int   g_idx1[43008];         // cb0 match: [0,32768) s0, [32768,40960) s1, [40960,43008) s2
__device__ float g_L1[43008];
__device__ int   g_idx2[32768];         // cb1 match on scale0
__device__ float g_Lb[32768];

// ---------------- downsample (bilinear, even factor == 2x2 avg with offset) ----------------
__global__ void ds_kernel(const float* __restrict__ img, int sel)
{
    // sel==0: f=2,o=0 -> g_img1 (128x128); sel==1: f=4,o=1 -> g_img2 (64x64)
    int Wout = sel ? 64 : 128;
    int f    = sel ? 4 : 2;
    int o    = sel ? 1 : 0;
    float* out = sel ? g_img2 : g_img1;
    int idx = blockIdx.x*blockDim.x + threadIdx.x;
    int total = 8*3*Wout*Wout;
    if (idx >= total) return;
    int x = idx % Wout, y = (idx / Wout) % Wout, bc = idx / (Wout*Wout);
    const float* p = img + (size_t)bc*256*256;
    int ry = y*f + o, rx = x*f + o;
    out[idx] = 0.25f*(p[ry*256+rx] + p[ry*256+rx+1] + p[(ry+1)*256+rx] + p[(ry+1)*256+rx+1]);
}

// ---------------- codebook squared norms ----------------
__global__ void cbsq_kernel(const float* __restrict__ cbs)
{
    int j = blockIdx.x*blockDim.x + threadIdx.x;
    if (j >= 2*KCB) return;
    const float* row = cbs + (size_t)j*CDIM;
    float s = 0.f;
    for (int c = 0; c < CDIM; c++) s += row[c]*row[c];
    g_cbsq[j] = s;
}

// ---------------- stride-4 4x4 conv, 3 in-ch -> 256 out-ch ----------------
// grid: (Hout, B); block: 256 threads (one per out channel).
// which: 0 -> (image ext, enc0 + NCHW out), 1 -> (g_img1, enc1), 2 -> (g_img2, enc2)
__global__ void __launch_bounds__(256) conv_kernel(
    const float* __restrict__ ext_img, const float* __restrict__ w,
    const float* __restrict__ bias, float* __restrict__ out_nchw, int which)
{
    __shared__ float ins[12][256];   // [ic*4+ky][x], Win <= 256
    int o = threadIdx.x;
    int y = blockIdx.x, b = blockIdx.y;
    int Hout = gridDim.x;
    int Win  = Hout * 4;

    const float* img = (which == 0) ? ext_img : (which == 1 ? g_img1 : g_img2);
    float* enc_nhwc  = (which == 0) ? g_enc0  : (which == 1 ? g_enc1 : g_enc2);

    int tot = 12*Win;
    for (int i = o; i < tot; i += 256) {
        int x = i % Win; int r = i / Win;      // r = ic*4 + ky
        ins[r][x] = img[(((size_t)b*3 + (r>>2))*Win + 4*y + (r&3))*Win + x];
    }
    float wreg[48];
    #pragma unroll
    for (int j = 0; j < 48; j++) wreg[j] = w[(size_t)o*48 + j];
    float bo = bias[o];
    __syncthreads();

    for (int x = 0; x < Hout; x++) {
        float acc = bo;
        #pragma unroll
        for (int j = 0; j < 48; j++) {
            int ic = j >> 4, ky = (j >> 2) & 3, kx = j & 3;
            acc += wreg[j] * ins[ic*4+ky][4*x+kx];
        }
        enc_nhwc[(((size_t)b*Hout + y)*Hout + x)*256 + o] = acc;
        if (which == 0) out_nchw[(((size_t)b*256 + o)*Hout + y)*Hout + x] = acc;
    }
}

// ---------------- distance + online softmax-reduce ----------------
// Per position: argmax_k s_k (first-index ties) and L = sum_k exp(s_k - max),
// with s_k = 2*dot(e,cb_k) - ||cb_k||^2. maxprob = 1/L.
// Block: 256 threads = 8 warps; 32 positions/block. Warp owns 4 positions,
// lanes cover 128 codes per k-chunk (lane + 32*m), 4 chunks.
// which: 0..2 -> E = enc{0,1,2}, cb0, out idx1/L1 (+offset); 3 -> enc0, cb1, idx2/Lb
__global__ void __launch_bounds__(256) dist_kernel(
    const float* __restrict__ cbs, int which, int pofs)
{
    const float* E  = (which == 1) ? g_enc1 : (which == 2 ? g_enc2 : g_enc0);
    const float* cb = cbs + (which == 3 ? (size_t)KCB*CDIM : 0);
    const float* sqg = g_cbsq + (which == 3 ? KCB : 0);
    int*   idxOut = (which == 3) ? g_idx2 : g_idx1;
    float* LOut   = (which == 3) ? g_Lb   : g_L1;

    __shared__ float Es[32][CDIM];     // 32 KB
    __shared__ float CBs[16][129];     // 8.06 KB padded: conflict-free
    __shared__ float sq[KCB];          // 2 KB
    int tid = threadIdx.x;
    int lane = tid & 31, warp = tid >> 5;
    int p0 = blockIdx.x * 32;

    for (int i = 0; i < 32; i++)
        Es[i][tid] = E[(size_t)(p0+i)*CDIM + tid];
    sq[tid]       = sqg[tid];
    sq[tid + 256] = sqg[tid + 256];

    const float NEG = -3.402823466e38f;
    float M[4], Lx[4]; int bi[4];
    #pragma unroll
    for (int j = 0; j < 4; j++) { M[j] = NEG; Lx[j] = 0.f; bi[j] = 0; }

    for (int kc = 0; kc < KCB; kc += 128) {
        float dot[4][4];
        #pragma unroll
        for (int j = 0; j < 4; j++)
            #pragma unroll
            for (int m = 0; m < 4; m++) dot[j][m] = 0.f;

        for (int cs = 0; cs < CDIM; cs += 16) {
            __syncthreads();
            #pragma unroll
            for (int i = 0; i < 8; i++) {
                int idx = i*256 + tid;
                int cc = idx & 15, kk = idx >> 4;
                CBs[cc][kk] = cb[(size_t)(kc+kk)*CDIM + cs + cc];
            }
            __syncthreads();
            #pragma unroll
            for (int c = 0; c < 16; c++) {
                float e0 = Es[warp*4+0][cs+c];
                float e1 = Es[warp*4+1][cs+c];
                float e2 = Es[warp*4+2][cs+c];
                float e3 = Es[warp*4+3][cs+c];
                float b0 = CBs[c][lane];
                float b1 = CBs[c][lane+32];
                float b2 = CBs[c][lane+64];
                float b3 = CBs[c][lane+96];
                dot[0][0] += e0*b0; dot[0][1] += e0*b1; dot[0][2] += e0*b2; dot[0][3] += e0*b3;
                dot[1][0] += e1*b0; dot[1][1] += e1*b1; dot[1][2] += e1*b2; dot[1][3] += e1*b3;
                dot[2][0] += e2*b0; dot[2][1] += e2*b1; dot[2][2] += e2*b2; dot[2][3] += e2*b3;
                dot[3][0] += e3*b0; dot[3][1] += e3*b1; dot[3][2] += e3*b2; dot[3][3] += e3*b3;
            }
        }
        // online update (codes per lane ascend in m and kc -> '>' keeps first max)
        #pragma unroll
        for (int j = 0; j < 4; j++) {
            #pragma unroll
            for (int m = 0; m < 4; m++) {
                int k = kc + lane + 32*m;
                float s = 2.f*dot[j][m] - sq[k];
                if (s > M[j]) { Lx[j] = Lx[j]*expf(M[j]-s) + 1.f; M[j] = s; bi[j] = k; }
                else          { Lx[j] += expf(s - M[j]); }
            }
        }
    }
    // warp butterfly reduce (max / argmax-first / stable sumexp)
    #pragma unroll
    for (int j = 0; j < 4; j++) {
        float m = M[j], l = Lx[j]; int id = bi[j];
        #pragma unroll
        for (int off = 16; off > 0; off >>= 1) {
            float m2 = __shfl_xor_sync(0xffffffffu, m, off);
            float l2 = __shfl_xor_sync(0xffffffffu, l, off);
            int  id2 = __shfl_xor_sync(0xffffffffu, id, off);
            float mn = fmaxf(m, m2);
            float ln = l*expf(m - mn) + l2*expf(m2 - mn);
            bool take = (m2 > m) || (m2 == m && id2 < id);
            id = take ? id2 : id;
            m = mn; l = ln;
        }
        if (lane == 0) { idxOut[pofs + p0 + warp*4 + j] = id; LOut[pofs + p0 + warp*4 + j] = l; }
    }
}

// ---------------- scale-select + zidx + STE output ----------------
// grid (16, 8), block 256: thread = (x = tid&63, y = blockIdx.x*4 + tid>>6), b = blockIdx.y
__global__ void __launch_bounds__(256) fuse_kernel(
    const float* __restrict__ cbs, float* __restrict__ out)
{
    const float* cb0 = cbs;
    const float* cb1 = cbs + (size_t)KCB*CDIM;
    int x = threadIdx.x & 63;
    int y = blockIdx.x*4 + (threadIdx.x >> 6);
    int b = blockIdx.y;
    int pos0 = (b*64 + y)*64 + x;
    int pos1 = 32768 + (b*32 + (y>>1))*32 + (x>>1);
    int pos2 = 40960 + (b*16 + (y>>2))*16 + (x>>2);
    // maxprob = 1/L; argmax over scales with first-index tie-break
    float pA = 1.f/g_L1[pos0], pB = 1.f/g_L1[pos1], pC = 1.f/g_L1[pos2];
    int z1 = g_idx1[pos0]; float best = pA;
    if (pB > best) { best = pB; z1 = g_idx1[pos1]; }
    if (pC > best) { best = pC; z1 = g_idx1[pos2]; }
    int z2 = g_idx2[pos0];

    out[OFF_Z + ((size_t)(b*2+0)*64 + y)*64 + x] = (float)z1;
    out[OFF_Z + ((size_t)(b*2+1)*64 + y)*64 + x] = (float)z2;

    const float4* r0 = (const float4*)(cb0 + (size_t)z1*CDIM);
    const float4* r1 = (const float4*)(cb1 + (size_t)z2*CDIM);
    size_t obase = (size_t)OFF_STE + (size_t)b*256*4096 + (size_t)y*64 + x;
    for (int c4 = 0; c4 < 64; c4++) {
        float4 a = r0[c4], q = r1[c4];
        int c = c4*4;
        out[obase + (size_t)(c+0)*4096] = 0.5f*(a.x + q.x);
        out[obase + (size_t)(c+1)*4096] = 0.5f*(a.y + q.y);
        out[obase + (size_t)(c+2)*4096] = 0.5f*(a.z + q.z);
        out[obase + (size_t)(c+3)*4096] = 0.5f*(a.w + q.w);
    }
}

// ---------------- launch ----------------
extern "C" void kernel_launch(void* const* d_in, const int* in_sizes, int n_in,
                              void* d_out, int out_size)
{
    const float* image     = (const float*)d_in[0];  // (8,3,256,256)
    const float* conv_w    = (const float*)d_in[1];  // (256,3,4,4)
    const float* conv_b    = (const float*)d_in[2];  // (256,)
    const float* codebooks = (const float*)d_in[3];  // (4,512,256)
    float* out = (float*)d_out;

    // downsample: 128x128 and 64x64
    ds_kernel<<<1536, 256>>>(image, 0);
    ds_kernel<<<384, 256>>>(image, 1);
    cbsq_kernel<<<4, 256>>>(codebooks);

    // conv at 3 scales (scale0 also writes NCHW output region 0)
    conv_kernel<<<dim3(64, 8), 256>>>(image, conv_w, conv_b, out, 0);
    conv_kernel<<<dim3(32, 8), 256>>>(image, conv_w, conv_b, out, 1);
    conv_kernel<<<dim3(16, 8), 256>>>(image, conv_w, conv_b, out, 2);

    // matches: cb0 on scales 0/1/2 (dedup'd positions), cb1 on scale0
    dist_kernel<<<1024, 256>>>(codebooks, 0, 0);
    dist_kernel<<<256, 256>>>(codebooks, 1, 32768);
    dist_kernel<<<64, 256>>>(codebooks, 2, 40960);
    dist_kernel<<<1024, 256>>>(codebooks, 3, 0);

    fuse_kernel<<<dim3(16, 8), 256>>>(codebooks, out);
}

// round 4
// speedup vs baseline: 1.2289x; 1.2289x over previous
#include <cuda_runtime.h>

#define CDIM 256
#define KCB  512

static const int N_ENC0  = 8*256*64*64;        // 8388608
static const int OFF_Z   = N_ENC0;
static const int OFF_STE = N_ENC0 + 8*2*64*64; // + 65536

typedef unsigned long long ull;

// ---- scratch (device globals; no allocation anywhere) ----
__device__ float g_img1[8*3*128*128];
__device__ float g_img2[8*3*64*64];
__device__ float g_enc0[8*64*64*256];   // NHWC scale0
__device__ float g_enc1[8*32*32*256];   // NHWC scale1
__device__ float g_enc2[8*16*16*256];   // NHWC scale2
__device__ float g_cbsq[2*KCB];
__device__ int   g_idx1[43008];         // cb0 match: [0,32768) s0, [32768,40960) s1, [40960,43008) s2
__device__ float g_L1[43008];
__device__ int   g_idx2[32768];         // cb1 match on scale0
__device__ float g_Lb[32768];

// ---- packed f32x2 helpers (FFMA2 only reachable via PTX) ----
__device__ __forceinline__ ull pk2(float lo, float hi) {
    ull r; asm("mov.b64 %0, {%1, %2};" : "=l"(r) : "f"(lo), "f"(hi)); return r;
}
__device__ __forceinline__ void upk2(ull v, float& lo, float& hi) {
    asm("mov.b64 {%0, %1}, %2;" : "=f"(lo), "=f"(hi) : "l"(v));
}
__device__ __forceinline__ void fma2(ull& d, ull a, ull b) {
    asm("fma.rn.f32x2 %0, %1, %2, %0;" : "+l"(d) : "l"(a), "l"(b));
}

// ---------------- downsample (bilinear, even factor == 2x2 avg with offset) ----------------
__global__ void ds_kernel(const float* __restrict__ img, int sel)
{
    int Wout = sel ? 64 : 128;
    int f    = sel ? 4 : 2;
    int o    = sel ? 1 : 0;
    float* out = sel ? g_img2 : g_img1;
    int idx = blockIdx.x*blockDim.x + threadIdx.x;
    int total = 8*3*Wout*Wout;
    if (idx >= total) return;
    int x = idx % Wout, y = (idx / Wout) % Wout, bc = idx / (Wout*Wout);
    const float* p = img + (size_t)bc*256*256;
    int ry = y*f + o, rx = x*f + o;
    out[idx] = 0.25f*(p[ry*256+rx] + p[ry*256+rx+1] + p[(ry+1)*256+rx] + p[(ry+1)*256+rx+1]);
}

// ---------------- codebook squared norms ----------------
__global__ void cbsq_kernel(const float* __restrict__ cbs)
{
    int j = blockIdx.x*blockDim.x + threadIdx.x;
    if (j >= 2*KCB) return;
    const float* row = cbs + (size_t)j*CDIM;
    float s = 0.f;
    for (int c = 0; c < CDIM; c++) s += row[c]*row[c];
    g_cbsq[j] = s;
}

// ---------------- stride-4 4x4 conv, 3 in-ch -> 256 out-ch (NHWC only) ----------------
// grid: (Hout, B); block: 256 threads (one per out channel).
__global__ void __launch_bounds__(256) conv_kernel(
    const float* __restrict__ ext_img, const float* __restrict__ w,
    const float* __restrict__ bias, int which)
{
    __shared__ float ins[12][256];
    int o = threadIdx.x;
    int y = blockIdx.x, b = blockIdx.y;
    int Hout = gridDim.x;
    int Win  = Hout * 4;

    const float* img = (which == 0) ? ext_img : (which == 1 ? g_img1 : g_img2);
    float* enc_nhwc  = (which == 0) ? g_enc0  : (which == 1 ? g_enc1 : g_enc2);

    int tot = 12*Win;
    for (int i = o; i < tot; i += 256) {
        int x = i % Win; int r = i / Win;      // r = ic*4 + ky
        ins[r][x] = img[(((size_t)b*3 + (r>>2))*Win + 4*y + (r&3))*Win + x];
    }
    float wreg[48];
    #pragma unroll
    for (int j = 0; j < 48; j++) wreg[j] = w[(size_t)o*48 + j];
    float bo = bias[o];
    __syncthreads();

    for (int x = 0; x < Hout; x++) {
        float acc = bo;
        #pragma unroll
        for (int j = 0; j < 48; j++) {
            int ic = j >> 4, ky = (j >> 2) & 3, kx = j & 3;
            acc += wreg[j] * ins[ic*4+ky][4*x+kx];
        }
        enc_nhwc[(((size_t)b*Hout + y)*Hout + x)*256 + o] = acc;
    }
}

// ---------------- NHWC -> NCHW transpose for enc0 into output region 0 ----------------
// grid (1024, 8): 32-pos x 32-ch tiles. out layout: [b][256][64][64], pos = b*4096 + p
__global__ void __launch_bounds__(256) transpose_kernel(float* __restrict__ out)
{
    __shared__ float t[32][33];
    int tid = threadIdx.x;
    int p0 = blockIdx.x * 32;
    int c0 = blockIdx.y * 32;
    #pragma unroll
    for (int it = 0; it < 4; it++) {
        int r = (tid >> 5) + it*8, cc = tid & 31;
        t[r][cc] = g_enc0[(size_t)(p0 + r)*256 + c0 + cc];
    }
    __syncthreads();
    #pragma unroll
    for (int it = 0; it < 4; it++) {
        int r = (tid >> 5) + it*8, pc = tid & 31;
        int gp = p0 + pc;
        int b = gp >> 12, p = gp & 4095;
        out[((size_t)b*256 + c0 + r)*4096 + p] = t[pc][r];
    }
}

// ---------------- fused distance + online softmax-reduce (packed f32x2) ----------------
// One launch covers all 4 matches. Block: 128 threads = 4 warps, 32 positions.
// Warp owns 8 positions; each lane owns 8 codes per 256-code chunk as 4 code-PAIRS
// (pair pi = lane + 32*mp -> codes 2pi, 2pi+1), accumulated in f32x2 halves.
// s_k = 2*dot(e,cb_k) - ||cb_k||^2 ; argmax (first-index ties) + L = sum exp(s-max).
__global__ void __launch_bounds__(128) dist_kernel(const float* __restrict__ cbs)
{
    __shared__ float Es[32][CDIM];        // 32 KB
    __shared__ float2 CBs[2][8][128];     // 16 KB (double-buffered 8-c tiles, XOR swizzled)

    int tid = threadIdx.x;
    int lane = tid & 31, warp = tid >> 5;
    int blk = blockIdx.x;

    const float *E, *cb, *sqg; int *idxOut; float *LOut; int prel, pofs;
    if (blk < 1024)      { E=g_enc0; cb=cbs;                  sqg=g_cbsq;     idxOut=g_idx1; LOut=g_L1; prel=blk*32;        pofs=prel; }
    else if (blk < 1280) { E=g_enc1; cb=cbs;                  sqg=g_cbsq;     idxOut=g_idx1; LOut=g_L1; prel=(blk-1024)*32; pofs=32768+prel; }
    else if (blk < 1344) { E=g_enc2; cb=cbs;                  sqg=g_cbsq;     idxOut=g_idx1; LOut=g_L1; prel=(blk-1280)*32; pofs=40960+prel; }
    else                 { E=g_enc0; cb=cbs+(size_t)KCB*CDIM; sqg=g_cbsq+KCB; idxOut=g_idx2; LOut=g_Lb; prel=(blk-1344)*32; pofs=prel; }

    // load 32 position vectors (coalesced; rows contiguous)
    for (int i = tid; i < 32*CDIM; i += 128)
        Es[0][i] = E[(size_t)prel*CDIM + i];

    const float NEG = -3.402823466e38f;
    float M[8], Lx[8]; int bi[8];
    #pragma unroll
    for (int j = 0; j < 8; j++) { M[j] = NEG; Lx[j] = 0.f; bi[j] = 0; }

    for (int kc = 0; kc < KCB; kc += 256) {
        ull acc[8][4];
        #pragma unroll
        for (int j = 0; j < 8; j++)
            #pragma unroll
            for (int mp = 0; mp < 4; mp++) acc[j][mp] = 0ULL;

        // prime tile 0 (cs = 0) into buf 0
        float pf[16];
        #pragma unroll
        for (int j = 0; j < 16; j++) {
            int lin = j*128 + tid;                 // 0..2047
            int k = lin >> 3, cc = lin & 7;
            pf[j] = cb[(size_t)(kc + k)*CDIM + cc];
        }
        if (kc == 0) __syncthreads();              // Es ready (first chunk only needs it once)
        #pragma unroll
        for (int j = 0; j < 16; j++) {
            int lin = j*128 + tid;
            int k = lin >> 3, cc = lin & 7;
            int pi = k >> 1, h = k & 1;
            ((float*)&CBs[0][cc][0])[2*((pi ^ (cc<<2)) & 127) + h] = pf[j];
        }
        __syncthreads();

        int buf = 0;
        for (int t = 0; t < 32; t++) {
            int cs = t*8;
            if (t < 31) {
                int cs2 = cs + 8;
                #pragma unroll
                for (int j = 0; j < 16; j++) {
                    int lin = j*128 + tid;
                    int k = lin >> 3, cc = lin & 7;
                    pf[j] = cb[(size_t)(kc + k)*CDIM + cs2 + cc];
                }
            }
            // compute on buf
            #pragma unroll
            for (int cc = 0; cc < 8; cc++) {
                ull epk[8];
                #pragma unroll
                for (int j = 0; j < 8; j++) {
                    float e = Es[warp*8 + j][cs + cc];
                    epk[j] = pk2(e, e);
                }
                const ull* row = (const ull*)&CBs[buf][cc][0];
                #pragma unroll
                for (int mp = 0; mp < 4; mp++) {
                    ull b2 = row[((lane + 32*mp) ^ (cc<<2)) & 127];
                    #pragma unroll
                    for (int j = 0; j < 8; j++) fma2(acc[j][mp], epk[j], b2);
                }
            }
            if (t < 31) {
                #pragma unroll
                for (int j = 0; j < 16; j++) {
                    int lin = j*128 + tid;
                    int k = lin >> 3, cc = lin & 7;
                    int pi = k >> 1, h = k & 1;
                    ((float*)&CBs[buf^1][cc][0])[2*((pi ^ (cc<<2)) & 127) + h] = pf[j];
                }
                __syncthreads();
                buf ^= 1;
            }
        }

        // online softmax update (codes ascend per lane: mp then chunk; pair lo<hi)
        #pragma unroll
        for (int mp = 0; mp < 4; mp++) {
            int pi = lane + 32*mp;
            int k0 = kc + 2*pi;
            float q0 = sqg[k0], q1 = sqg[k0 + 1];
            #pragma unroll
            for (int j = 0; j < 8; j++) {
                float lo, hi; upk2(acc[j][mp], lo, hi);
                float s0 = 2.f*lo - q0;
                float s1 = 2.f*hi - q1;
                if (s0 > M[j]) { Lx[j] = Lx[j]*expf(M[j]-s0) + 1.f; M[j] = s0; bi[j] = k0; }
                else           { Lx[j] += expf(s0 - M[j]); }
                if (s1 > M[j]) { Lx[j] = Lx[j]*expf(M[j]-s1) + 1.f; M[j] = s1; bi[j] = k0+1; }
                else           { Lx[j] += expf(s1 - M[j]); }
            }
        }
    }

    // warp butterfly reduce (max / argmax-first / stable sumexp)
    #pragma unroll
    for (int j = 0; j < 8; j++) {
        float m = M[j], l = Lx[j]; int id = bi[j];
        #pragma unroll
        for (int off = 16; off > 0; off >>= 1) {
            float m2 = __shfl_xor_sync(0xffffffffu, m, off);
            float l2 = __shfl_xor_sync(0xffffffffu, l, off);
            int  id2 = __shfl_xor_sync(0xffffffffu, id, off);
            float mn = fmaxf(m, m2);
            float ln = l*expf(m - mn) + l2*expf(m2 - mn);
            bool take = (m2 > m) || (m2 == m && id2 < id);
            id = take ? id2 : id;
            m = mn; l = ln;
        }
        if (lane == 0) {
            idxOut[pofs + warp*8 + j] = id;
            LOut[pofs + warp*8 + j]   = l;
        }
    }
}

// ---------------- scale-select + zidx + STE output ----------------
__global__ void __launch_bounds__(256) fuse_kernel(
    const float* __restrict__ cbs, float* __restrict__ out)
{
    const float* cb0 = cbs;
    const float* cb1 = cbs + (size_t)KCB*CDIM;
    int x = threadIdx.x & 63;
    int y = blockIdx.x*4 + (threadIdx.x >> 6);
    int b = blockIdx.y;
    int pos0 = (b*64 + y)*64 + x;
    int pos1 = 32768 + (b*32 + (y>>1))*32 + (x>>1);
    int pos2 = 40960 + (b*16 + (y>>2))*16 + (x>>2);
    float pA = 1.f/g_L1[pos0], pB = 1.f/g_L1[pos1], pC = 1.f/g_L1[pos2];
    int z1 = g_idx1[pos0]; float best = pA;
    if (pB > best) { best = pB; z1 = g_idx1[pos1]; }
    if (pC > best) { best = pC; z1 = g_idx1[pos2]; }
    int z2 = g_idx2[pos0];

    out[OFF_Z + ((size_t)(b*2+0)*64 + y)*64 + x] = (float)z1;
    out[OFF_Z + ((size_t)(b*2+1)*64 + y)*64 + x] = (float)z2;

    const float4* r0 = (const float4*)(cb0 + (size_t)z1*CDIM);
    const float4* r1 = (const float4*)(cb1 + (size_t)z2*CDIM);
    size_t obase = (size_t)OFF_STE + (size_t)b*256*4096 + (size_t)y*64 + x;
    for (int c4 = 0; c4 < 64; c4++) {
        float4 a = r0[c4], q = r1[c4];
        int c = c4*4;
        out[obase + (size_t)(c+0)*4096] = 0.5f*(a.x + q.x);
        out[obase + (size_t)(c+1)*4096] = 0.5f*(a.y + q.y);
        out[obase + (size_t)(c+2)*4096] = 0.5f*(a.z + q.z);
        out[obase + (size_t)(c+3)*4096] = 0.5f*(a.w + q.w);
    }
}

// ---------------- launch ----------------
extern "C" void kernel_launch(void* const* d_in, const int* in_sizes, int n_in,
                              void* d_out, int out_size)
{
    const float* image     = (const float*)d_in[0];  // (8,3,256,256)
    const float* conv_w    = (const float*)d_in[1];  // (256,3,4,4)
    const float* conv_b    = (const float*)d_in[2];  // (256,)
    const float* codebooks = (const float*)d_in[3];  // (4,512,256)
    float* out = (float*)d_out;

    ds_kernel<<<1536, 256>>>(image, 0);
    ds_kernel<<<384, 256>>>(image, 1);
    cbsq_kernel<<<4, 256>>>(codebooks);

    conv_kernel<<<dim3(64, 8), 256>>>(image, conv_w, conv_b, 0);
    conv_kernel<<<dim3(32, 8), 256>>>(image, conv_w, conv_b, 1);
    conv_kernel<<<dim3(16, 8), 256>>>(image, conv_w, conv_b, 2);

    transpose_kernel<<<dim3(1024, 8), 256>>>(out);

    // one fused launch: cb0 x {enc0,enc1,enc2} + cb1 x enc0
    dist_kernel<<<2368, 128>>>(codebooks);

    fuse_kernel<<<dim3(16, 8), 256>>>(codebooks, out);
}

// round 6
// speedup vs baseline: 1.4048x; 1.1432x over previous
#include <cuda_runtime.h>
#include <cstdint>

#define CDIM 256
#define KCB  512

static const int N_ENC0  = 8*256*64*64;        // 8388608
static const int OFF_Z   = N_ENC0;
static const int OFF_STE = N_ENC0 + 8*2*64*64; // + 65536

// ---- scratch (device globals; no allocation anywhere) ----
__device__ float g_img1[8*3*128*128];
__device__ float g_img2[8*3*64*64];
__device__ float g_enc0[8*64*64*256];   // NHWC scale0
__device__ float g_enc1[8*32*32*256];   // NHWC scale1
__device__ float g_enc2[8*16*16*256];   // NHWC scale2
__device__ float g_cbsq[2*KCB];         // ||cb||^2, 1024 rows
// tf32 2-split operands, k-PERMUTED within each 32-chunk: kperm = (k&3)*8 + ((k&31)>>2)
__device__ float g_ehi[43008*256];      // concat enc0|enc1|enc2 rows
__device__ float g_elo[43008*256];
__device__ float g_cbhi[1024*256];      // cb0 rows 0..511, cb1 rows 512..1023
__device__ float g_cblo[1024*256];
// per-(quarter, position) partials: cb0: q*43008 + pos ; cb1: 172032 + q*32768 + pos
__device__ float g_hM[303104];
__device__ float g_hL[303104];
__device__ int   g_hI[303104];

__device__ __forceinline__ float tf32_rna(float f) {
    uint32_t r; asm("cvt.rna.tf32.f32 %0, %1;" : "=r"(r) : "f"(f));
    return __uint_as_float(r);
}

// m16n8k8 tf32 MMA (sm_80+ PTX -> fallback HMMA on sm_103a)
// a0=A[g][t4] a1=A[g+8][t4] a2=A[g][t4+4] a3=A[g+8][t4+4]; b0=B[t4][n] b1=B[t4+4][n]
__device__ __forceinline__ void mma_tf32(float* c, float2 a0, float2 a1, float2 b) {
    asm volatile("mma.sync.aligned.m16n8k8.row.col.f32.tf32.tf32.f32 "
        "{%0,%1,%2,%3}, {%4,%5,%6,%7}, {%8,%9}, {%0,%1,%2,%3};"
        : "+f"(c[0]), "+f"(c[1]), "+f"(c[2]), "+f"(c[3])
        : "r"(__float_as_uint(a0.x)), "r"(__float_as_uint(a1.x)),
          "r"(__float_as_uint(a0.y)), "r"(__float_as_uint(a1.y)),
          "r"(__float_as_uint(b.x)),  "r"(__float_as_uint(b.y)));
}

// ======================= small kernels =======================
__global__ void ds_kernel(const float* __restrict__ img, int sel)
{
    int Wout = sel ? 64 : 128;
    int f    = sel ? 4 : 2;
    int o    = sel ? 1 : 0;
    float* out = sel ? g_img2 : g_img1;
    int idx = blockIdx.x*blockDim.x + threadIdx.x;
    int total = 8*3*Wout*Wout;
    if (idx >= total) return;
    int x = idx % Wout, y = (idx / Wout) % Wout, bc = idx / (Wout*Wout);
    const float* p = img + (size_t)bc*256*256;
    int ry = y*f + o, rx = x*f + o;
    out[idx] = 0.25f*(p[ry*256+rx] + p[ry*256+rx+1] + p[(ry+1)*256+rx] + p[(ry+1)*256+rx+1]);
}

__global__ void cbsq_kernel(const float* __restrict__ cbs)
{
    int j = blockIdx.x*blockDim.x + threadIdx.x;
    if (j >= 2*KCB) return;
    const float* row = cbs + (size_t)j*CDIM;
    float s = 0.f;
    for (int c = 0; c < CDIM; c++) s += row[c]*row[c];
    g_cbsq[j] = s;
}

// stride-4 4x4 conv, 3 in-ch -> 256 out-ch (NHWC)
__global__ void __launch_bounds__(256) conv_kernel(
    const float* __restrict__ ext_img, const float* __restrict__ w,
    const float* __restrict__ bias, int which)
{
    __shared__ float ins[12][256];
    int o = threadIdx.x;
    int y = blockIdx.x, b = blockIdx.y;
    int Hout = gridDim.x;
    int Win  = Hout * 4;

    const float* img = (which == 0) ? ext_img : (which == 1 ? g_img1 : g_img2);
    float* enc_nhwc  = (which == 0) ? g_enc0  : (which == 1 ? g_enc1 : g_enc2);

    int tot = 12*Win;
    for (int i = o; i < tot; i += 256) {
        int x = i % Win; int r = i / Win;
        ins[r][x] = img[(((size_t)b*3 + (r>>2))*Win + 4*y + (r&3))*Win + x];
    }
    float wreg[48];
    #pragma unroll
    for (int j = 0; j < 48; j++) wreg[j] = w[(size_t)o*48 + j];
    float bo = bias[o];
    __syncthreads();

    for (int x = 0; x < Hout; x++) {
        float acc = bo;
        #pragma unroll
        for (int j = 0; j < 48; j++) {
            int ic = j >> 4, ky = (j >> 2) & 3, kx = j & 3;
            acc += wreg[j] * ins[ic*4+ky][4*x+kx];
        }
        enc_nhwc[(((size_t)b*Hout + y)*Hout + x)*256 + o] = acc;
    }
}

// NHWC -> NCHW transpose for enc0 into output region 0
__global__ void __launch_bounds__(256) transpose_kernel(float* __restrict__ out)
{
    __shared__ float t[32][33];
    int tid = threadIdx.x;
    int p0 = blockIdx.x * 32;
    int c0 = blockIdx.y * 32;
    #pragma unroll
    for (int it = 0; it < 4; it++) {
        int r = (tid >> 5) + it*8, cc = tid & 31;
        t[r][cc] = g_enc0[(size_t)(p0 + r)*256 + c0 + cc];
    }
    __syncthreads();
    #pragma unroll
    for (int it = 0; it < 4; it++) {
        int r = (tid >> 5) + it*8, pc = tid & 31;
        int gp = p0 + pc;
        int b = gp >> 12, p = gp & 4095;
        out[((size_t)b*256 + c0 + r)*4096 + p] = t[pc][r];
    }
}

// tf32 hi/lo split (k-permuted layout) of encodings (43008 rows) + codebooks (1024 rows)
__global__ void __launch_bounds__(256) split_kernel(const float* __restrict__ cbs)
{
    int row = blockIdx.x, k = threadIdx.x;
    float v; float* hi; float* lo; size_t rbase;
    if (row < 43008) {
        if (row < 32768)      v = g_enc0[(size_t)row*256 + k];
        else if (row < 40960) v = g_enc1[(size_t)(row-32768)*256 + k];
        else                  v = g_enc2[(size_t)(row-40960)*256 + k];
        hi = g_ehi; lo = g_elo; rbase = (size_t)row*256;
    } else {
        int r = row - 43008;
        v = cbs[(size_t)r*256 + k];
        hi = g_cbhi; lo = g_cblo; rbase = (size_t)r*256;
    }
    float h = tf32_rna(v);
    float l = tf32_rna(v - h);
    int kk = k & 31;
    size_t o = rbase + (k & ~31) + ((kk & 3) << 3) + (kk >> 2);
    hi[o] = h; lo[o] = l;
}

// ======================= tf32 mma.sync distance =======================
// CTA: M=128 positions x N=128 codes (quarter codebook), K=256 (8 chunks of 32).
// dot ~= Ahi*Bhi + Ahi*Blo + Alo*Bhi. 8 warps: wm=w&1 (M 64), wn=w>>1 (N 32).
#define STR 34                          // smem row stride in floats (bank-optimal, 8B aligned)
#define TILEF (128*STR)                 // 4352 floats per operand buffer
#define DSMEM ((4*TILEF + 128)*4)       // 70144 bytes

__global__ void __launch_bounds__(256, 1) dist_mma_kernel()
{
    extern __shared__ float smf[];
    float* Ahi = smf;
    float* Alo = smf + TILEF;
    float* Bhi = smf + 2*TILEF;
    float* Blo = smf + 3*TILEF;
    float* cbs_s = smf + 4*TILEF;       // 128 floats

    int tid = threadIdx.x;
    int lane = tid & 31, w = tid >> 5;
    int g = lane >> 2, t4 = lane & 3;
    int wm = w & 1, wn = w >> 1;

    int blk = blockIdx.x;
    int seg, mtile, q;
    if (blk < 1344) { seg = 0; mtile = blk >> 2; q = blk & 3; }
    else            { seg = 1; mtile = (blk - 1344) >> 2; q = (blk - 1344) & 3; }

    const float* Ahi_g = g_ehi + (size_t)mtile*128*256;
    const float* Alo_g = g_elo + (size_t)mtile*128*256;
    int cbrow = (seg ? 512 : 0) + q*128;
    const float* Bhi_g = g_cbhi + (size_t)cbrow*256;
    const float* Blo_g = g_cblo + (size_t)cbrow*256;

    if (tid < 128) cbs_s[tid] = g_cbsq[cbrow + tid];

    float acc[4][4][4];
    #pragma unroll
    for (int mt = 0; mt < 4; mt++)
        #pragma unroll
        for (int u = 0; u < 4; u++)
            #pragma unroll
            for (int e = 0; e < 4; e++) acc[mt][u][e] = 0.f;

    int abase = (wm*64 + g)*STR + t4*8;   // A frag base (row g of warp m-range)
    int bbase = (wn*32 + g)*STR + t4*8;   // B frag base

    for (int kc = 0; kc < 8; kc++) {
        if (kc > 0) __syncthreads();
        // stage chunk: 128 rows x 32 floats per operand, permuted k is contiguous
        int r = tid >> 3, qq = tid & 7;
        #pragma unroll
        for (int it = 0; it < 4; it++) {
            int rr = r + it*32;
            size_t so = (size_t)rr*256 + kc*32 + qq*4;
            int  dof = rr*STR + qq*4;
            float4 v;
            v = *(const float4*)(Ahi_g + so);
            *(float2*)(Ahi + dof) = make_float2(v.x, v.y);
            *(float2*)(Ahi + dof + 2) = make_float2(v.z, v.w);
            v = *(const float4*)(Alo_g + so);
            *(float2*)(Alo + dof) = make_float2(v.x, v.y);
            *(float2*)(Alo + dof + 2) = make_float2(v.z, v.w);
            v = *(const float4*)(Bhi_g + so);
            *(float2*)(Bhi + dof) = make_float2(v.x, v.y);
            *(float2*)(Bhi + dof + 2) = make_float2(v.z, v.w);
            v = *(const float4*)(Blo_g + so);
            *(float2*)(Blo + dof) = make_float2(v.x, v.y);
            *(float2*)(Blo + dof + 2) = make_float2(v.z, v.w);
        }
        __syncthreads();

        #pragma unroll
        for (int s = 0; s < 4; s++) {
            int ko = 2*s;
            float2 ah[4][2], al[4][2], bh[4], bl[4];
            #pragma unroll
            for (int mt = 0; mt < 4; mt++) {
                ah[mt][0] = *(float2*)(Ahi + abase + mt*16*STR + ko);
                ah[mt][1] = *(float2*)(Ahi + abase + (mt*16+8)*STR + ko);
                al[mt][0] = *(float2*)(Alo + abase + mt*16*STR + ko);
                al[mt][1] = *(float2*)(Alo + abase + (mt*16+8)*STR + ko);
            }
            #pragma unroll
            for (int u = 0; u < 4; u++) {
                bh[u] = *(float2*)(Bhi + bbase + u*8*STR + ko);
                bl[u] = *(float2*)(Blo + bbase + u*8*STR + ko);
            }
            #pragma unroll
            for (int mt = 0; mt < 4; mt++)
                #pragma unroll
                for (int u = 0; u < 4; u++) {
                    mma_tf32(acc[mt][u], ah[mt][0], ah[mt][1], bh[u]);
                    mma_tf32(acc[mt][u], ah[mt][0], ah[mt][1], bl[u]);
                    mma_tf32(acc[mt][u], al[mt][0], al[mt][1], bh[u]);
                }
        }
    }
    __syncthreads();

    // partial overlay in smem (Ahi region is dead now)
    float* Mp = smf;            // [128][4]
    float* Lp = smf + 512;
    int*   Ip = (int*)(smf + 1024);

    const float NEG = -3.402823466e38f;
    #pragma unroll
    for (int mt = 0; mt < 4; mt++) {
        #pragma unroll
        for (int half = 0; half < 2; half++) {
            int row = wm*64 + mt*16 + g + half*8;
            float M = NEG, L = 0.f; int I = 0;
            #pragma unroll
            for (int u = 0; u < 4; u++) {
                #pragma unroll
                for (int j = 0; j < 2; j++) {
                    int col = wn*32 + u*8 + 2*t4 + j;
                    float s = 2.f*acc[mt][u][half*2 + j] - cbs_s[col];
                    if (s > M) { L = L*expf(M - s) + 1.f; M = s; I = col; }
                    else       { L += expf(s - M); }
                }
            }
            // reduce over the 4 t4-lanes (same g)
            #pragma unroll
            for (int off = 1; off <= 2; off <<= 1) {
                float m2 = __shfl_xor_sync(0xffffffffu, M, off);
                float l2 = __shfl_xor_sync(0xffffffffu, L, off);
                int   i2 = __shfl_xor_sync(0xffffffffu, I, off);
                float mn = fmaxf(M, m2);
                L = L*expf(M - mn) + l2*expf(m2 - mn);
                if (m2 > M || (m2 == M && i2 < I)) I = i2;
                M = mn;
            }
            if (t4 == 0) { Mp[row*4 + wn] = M; Lp[row*4 + wn] = L; Ip[row*4 + wn] = I; }
        }
    }
    __syncthreads();

    if (tid < 128) {
        float M = Mp[tid*4], L = Lp[tid*4]; int I = Ip[tid*4];
        #pragma unroll
        for (int n = 1; n < 4; n++) {
            float m2 = Mp[tid*4 + n], l2 = Lp[tid*4 + n];
            float mn = fmaxf(M, m2);
            L = L*expf(M - mn) + l2*expf(m2 - mn);
            if (m2 > M) I = Ip[tid*4 + n];   // ascending col blocks: ties keep first
            M = mn;
        }
        int pos = mtile*128 + tid;
        int slot = seg ? (172032 + q*32768 + pos) : (q*43008 + pos);
        g_hM[slot] = M; g_hL[slot] = L; g_hI[slot] = q*128 + I;
    }
}

// ======================= fuse =======================
__device__ __forceinline__ void merge4(int pos, int base, int stride, float& P, int& idx)
{
    float M = g_hM[base + pos], L = g_hL[base + pos]; int I = g_hI[base + pos];
    #pragma unroll
    for (int n = 1; n < 4; n++) {
        int s = base + n*stride + pos;
        float m2 = g_hM[s], l2 = g_hL[s];
        float mn = fmaxf(M, m2);
        L = L*expf(M - mn) + l2*expf(m2 - mn);
        if (m2 > M) I = g_hI[s];     // ascending quarters: ties keep first
        M = mn;
    }
    P = 1.f / L; idx = I;
}

__global__ void __launch_bounds__(256) fuse_kernel(
    const float* __restrict__ cbs, float* __restrict__ out)
{
    const float* cb0 = cbs;
    const float* cb1 = cbs + (size_t)KCB*CDIM;
    int x = threadIdx.x & 63;
    int y = blockIdx.x*4 + (threadIdx.x >> 6);
    int b = blockIdx.y;
    int pos0 = (b*64 + y)*64 + x;
    int pos1 = 32768 + (b*32 + (y>>1))*32 + (x>>1);
    int pos2 = 40960 + (b*16 + (y>>2))*16 + (x>>2);

    float pA, pB, pC; int zA, zB, zC;
    merge4(pos0, 0, 43008, pA, zA);
    merge4(pos1, 0, 43008, pB, zB);
    merge4(pos2, 0, 43008, pC, zC);
    int z1 = zA; float best = pA;
    if (pB > best) { best = pB; z1 = zB; }
    if (pC > best) { best = pC; z1 = zC; }
    float p2d; int z2;
    merge4(pos0, 172032, 32768, p2d, z2);

    out[OFF_Z + ((size_t)(b*2+0)*64 + y)*64 + x] = (float)z1;
    out[OFF_Z + ((size_t)(b*2+1)*64 + y)*64 + x] = (float)z2;

    const float4* r0 = (const float4*)(cb0 + (size_t)z1*CDIM);
    const float4* r1 = (const float4*)(cb1 + (size_t)z2*CDIM);
    size_t obase = (size_t)OFF_STE + (size_t)b*256*4096 + (size_t)y*64 + x;
    for (int c4 = 0; c4 < 64; c4++) {
        float4 a = r0[c4], qv = r1[c4];
        int c = c4*4;
        out[obase + (size_t)(c+0)*4096] = 0.5f*(a.x + qv.x);
        out[obase + (size_t)(c+1)*4096] = 0.5f*(a.y + qv.y);
        out[obase + (size_t)(c+2)*4096] = 0.5f*(a.z + qv.z);
        out[obase + (size_t)(c+3)*4096] = 0.5f*(a.w + qv.w);
    }
}

// ======================= launch =======================
extern "C" void kernel_launch(void* const* d_in, const int* in_sizes, int n_in,
                              void* d_out, int out_size)
{
    const float* image     = (const float*)d_in[0];  // (8,3,256,256)
    const float* conv_w    = (const float*)d_in[1];  // (256,3,4,4)
    const float* conv_b    = (const float*)d_in[2];  // (256,)
    const float* codebooks = (const float*)d_in[3];  // (4,512,256)
    float* out = (float*)d_out;

    cudaFuncSetAttribute(dist_mma_kernel, cudaFuncAttributeMaxDynamicSharedMemorySize, DSMEM);

    ds_kernel<<<1536, 256>>>(image, 0);
    ds_kernel<<<384, 256>>>(image, 1);
    cbsq_kernel<<<4, 256>>>(codebooks);

    conv_kernel<<<dim3(64, 8), 256>>>(image, conv_w, conv_b, 0);
    conv_kernel<<<dim3(32, 8), 256>>>(image, conv_w, conv_b, 1);
    conv_kernel<<<dim3(16, 8), 256>>>(image, conv_w, conv_b, 2);

    transpose_kernel<<<dim3(1024, 8), 256>>>(out);
    split_kernel<<<44032, 256>>>(codebooks);

    // cb0: 336 mtiles x 4 quarters = 1344 ; cb1: 256 x 4 = 1024
    dist_mma_kernel<<<2368, 256, DSMEM>>>();

    fuse_kernel<<<dim3(16, 8), 256>>>(codebooks, out);
}

// round 10
// speedup vs baseline: 2.2420x; 1.5959x over previous
#include <cuda_runtime.h>
#include <cuda_fp16.h>
#include <cstdint>

#define CDIM 256
#define KCB  512

static const int N_ENC0  = 8*256*64*64;        // 8388608
static const int OFF_Z   = N_ENC0;
static const int OFF_STE = N_ENC0 + 8*2*64*64; // + 65536

// ---- scratch (device globals; no allocation anywhere) ----
__device__ float g_img1[8*3*128*128];
__device__ float g_img2[8*3*64*64];
__device__ float g_enc0[8*64*64*256];   // NHWC scale0
__device__ float g_enc1[8*32*32*256];   // NHWC scale1
__device__ float g_enc2[8*16*16*256];   // NHWC scale2
__device__ float g_cbsq[2*KCB];         // ||cb||^2, 1024 rows
// fp16 hi/lo split operands, k-PERMUTED within each 16-chunk:
// j=k&15 -> slot = ((j&7)>>1)*4 + ((j>>3)<<1) + (j&1)   (lane t4 owns slots 4t4..4t4+3)
__device__ __half g_ehi[43008*256];     // concat enc0|enc1|enc2 rows
__device__ __half g_elo[43008*256];
__device__ __half g_cbhi[1024*256];     // cb0 rows 0..511, cb1 rows 512..1023
__device__ __half g_cblo[1024*256];
// per-(quarter, position) partials: cb0: q*43008 + pos ; cb1: 172032 + q*32768 + pos
__device__ float g_hM[303104];
__device__ float g_hL[303104];
__device__ int   g_hI[303104];

// m16n8k16 fp16 MMA, fp32 accum (sm_80+ PTX)
__device__ __forceinline__ void mma_f16(float* c, uint2 a01, uint2 a23, uint2 b) {
    asm volatile("mma.sync.aligned.m16n8k16.row.col.f32.f16.f16.f32 "
        "{%0,%1,%2,%3}, {%4,%5,%6,%7}, {%8,%9}, {%0,%1,%2,%3};"
        : "+f"(c[0]), "+f"(c[1]), "+f"(c[2]), "+f"(c[3])
        : "r"(a01.x), "r"(a23.x), "r"(a01.y), "r"(a23.y),
          "r"(b.x),  "r"(b.y));
}

// ======================= small kernels =======================
__global__ void ds_kernel(const float* __restrict__ img, int sel)
{
    int Wout = sel ? 64 : 128;
    int f    = sel ? 4 : 2;
    int o    = sel ? 1 : 0;
    float* out = sel ? g_img2 : g_img1;
    int idx = blockIdx.x*blockDim.x + threadIdx.x;
    int total = 8*3*Wout*Wout;
    if (idx >= total) return;
    int x = idx % Wout, y = (idx / Wout) % Wout, bc = idx / (Wout*Wout);
    const float* p = img + (size_t)bc*256*256;
    int ry = y*f + o, rx = x*f + o;
    out[idx] = 0.25f*(p[ry*256+rx] + p[ry*256+rx+1] + p[(ry+1)*256+rx] + p[(ry+1)*256+rx+1]);
}

__global__ void cbsq_kernel(const float* __restrict__ cbs)
{
    int j = blockIdx.x*blockDim.x + threadIdx.x;
    if (j >= 2*KCB) return;
    const float* row = cbs + (size_t)j*CDIM;
    float s = 0.f;
    for (int c = 0; c < CDIM; c++) s += row[c]*row[c];
    g_cbsq[j] = s;
}

// stride-4 4x4 conv, 3 in-ch -> 256 out-ch (NHWC)
__global__ void __launch_bounds__(256) conv_kernel(
    const float* __restrict__ ext_img, const float* __restrict__ w,
    const float* __restrict__ bias, int which)
{
    __shared__ float ins[12][256];
    int o = threadIdx.x;
    int y = blockIdx.x, b = blockIdx.y;
    int Hout = gridDim.x;
    int Win  = Hout * 4;

    const float* img = (which == 0) ? ext_img : (which == 1 ? g_img1 : g_img2);
    float* enc_nhwc  = (which == 0) ? g_enc0  : (which == 1 ? g_enc1 : g_enc2);

    int tot = 12*Win;
    for (int i = o; i < tot; i += 256) {
        int x = i % Win; int r = i / Win;
        ins[r][x] = img[(((size_t)b*3 + (r>>2))*Win + 4*y + (r&3))*Win + x];
    }
    float wreg[48];
    #pragma unroll
    for (int j = 0; j < 48; j++) wreg[j] = w[(size_t)o*48 + j];
    float bo = bias[o];
    __syncthreads();

    for (int x = 0; x < Hout; x++) {
        float acc = bo;
        #pragma unroll
        for (int j = 0; j < 48; j++) {
            int ic = j >> 4, ky = (j >> 2) & 3, kx = j & 3;
            acc += wreg[j] * ins[ic*4+ky][4*x+kx];
        }
        enc_nhwc[(((size_t)b*Hout + y)*Hout + x)*256 + o] = acc;
    }
}

// NHWC -> NCHW transpose for enc0 into output region 0
__global__ void __launch_bounds__(256) transpose_kernel(float* __restrict__ out)
{
    __shared__ float t[32][33];
    int tid = threadIdx.x;
    int p0 = blockIdx.x * 32;
    int c0 = blockIdx.y * 32;
    #pragma unroll
    for (int it = 0; it < 4; it++) {
        int r = (tid >> 5) + it*8, cc = tid & 31;
        t[r][cc] = g_enc0[(size_t)(p0 + r)*256 + c0 + cc];
    }
    __syncthreads();
    #pragma unroll
    for (int it = 0; it < 4; it++) {
        int r = (tid >> 5) + it*8, pc = tid & 31;
        int gp = p0 + pc;
        int b = gp >> 12, p = gp & 4095;
        out[((size_t)b*256 + c0 + r)*4096 + p] = t[pc][r];
    }
}

// fp16 hi/lo split (k-permuted) of encodings (43008 rows) + codebooks (1024 rows)
__global__ void __launch_bounds__(256) split_kernel(const float* __restrict__ cbs)
{
    int row = blockIdx.x, k = threadIdx.x;
    float v; __half* hi; __half* lo; size_t rbase;
    if (row < 43008) {
        if (row < 32768)      v = g_enc0[(size_t)row*256 + k];
        else if (row < 40960) v = g_enc1[(size_t)(row-32768)*256 + k];
        else                  v = g_enc2[(size_t)(row-40960)*256 + k];
        hi = g_ehi; lo = g_elo; rbase = (size_t)row*256;
    } else {
        int r = row - 43008;
        v = cbs[(size_t)r*256 + k];
        hi = g_cbhi; lo = g_cblo; rbase = (size_t)r*256;
    }
    __half h = __float2half_rn(v);
    __half l = __float2half_rn(v - __half2float(h));
    int j = k & 15;
    int slot = ((j & 7) >> 1)*4 + ((j >> 3) << 1) + (j & 1);
    size_t o = rbase + (k & ~15) + slot;
    hi[o] = h; lo[o] = l;
}

// ======================= fp16 mma.sync distance =======================
// CTA: M=128 positions x N=128 codes (quarter codebook), K=256 in 8 chunks of 32.
// dot ~= Ahi*Bhi + Ahi*Blo + Alo*Bhi (all products exact in fp32 accum; dropped lo*lo ~2^-22).
// 8 warps: wm=w&1 (M 64), wn=w>>1 (N 32). Warp tile 64x32, 3 x m16n8k16 per (mt,u).
#define STRH 80                         // smem row stride in halves (160B: banks = 4g+t4, conflict-free)
#define TILEH (128*STRH)                // 10240 halves = 20480 B per operand
#define DSMEM (4*TILEH*2 + 512)        // 82432 bytes

__global__ void __launch_bounds__(256) dist_mma_kernel()
{
    extern __shared__ char smem[];
    __half* sAhi = (__half*)smem;
    __half* sAlo = sAhi + TILEH;
    __half* sBhi = sAlo + TILEH;
    __half* sBlo = sBhi + TILEH;
    float*  cbs_s = (float*)(smem + 4*TILEH*2);   // 128 floats

    int tid = threadIdx.x;
    int lane = tid & 31, w = tid >> 5;
    int g = lane >> 2, t4 = lane & 3;
    int wm = w & 1, wn = w >> 1;

    int blk = blockIdx.x;
    int seg, mtile, q;
    if (blk < 1344) { seg = 0; mtile = blk >> 2; q = blk & 3; }
    else            { seg = 1; mtile = (blk - 1344) >> 2; q = (blk - 1344) & 3; }

    const __half* Ahi_g = g_ehi + (size_t)mtile*128*256;
    const __half* Alo_g = g_elo + (size_t)mtile*128*256;
    int cbrow = (seg ? 512 : 0) + q*128;
    const __half* Bhi_g = g_cbhi + (size_t)cbrow*256;
    const __half* Blo_g = g_cblo + (size_t)cbrow*256;

    if (tid < 128) cbs_s[tid] = g_cbsq[cbrow + tid];

    float acc[4][4][4];
    #pragma unroll
    for (int mt = 0; mt < 4; mt++)
        #pragma unroll
        for (int u = 0; u < 4; u++)
            #pragma unroll
            for (int e = 0; e < 4; e++) acc[mt][u][e] = 0.f;

    const __half* gsrc[4] = {Ahi_g, Alo_g, Bhi_g, Blo_g};
    __half* sdst[4] = {sAhi, sAlo, sBhi, sBlo};

    for (int kc = 0; kc < 8; kc++) {
        if (kc > 0) __syncthreads();
        // stage: per operand 128 rows x 32 halves (64B = 4 x uint4)
        #pragma unroll
        for (int op = 0; op < 4; op++) {
            #pragma unroll
            for (int it = 0; it < 2; it++) {
                int c = it*256 + tid;
                int r = c >> 2, sgs = c & 3;
                *(uint4*)(sdst[op] + r*STRH + sgs*8) =
                    *(const uint4*)(gsrc[op] + (size_t)r*256 + kc*32 + sgs*8);
            }
        }
        __syncthreads();

        #pragma unroll
        for (int s = 0; s < 2; s++) {
            int ko = s*16 + t4*4;
            uint2 ahf[4][2], alf[4][2], bhf[4], blf[4];
            #pragma unroll
            for (int mt = 0; mt < 4; mt++) {
                int ar = (wm*64 + mt*16 + g)*STRH + ko;
                ahf[mt][0] = *(uint2*)(sAhi + ar);
                ahf[mt][1] = *(uint2*)(sAhi + ar + 8*STRH);
                alf[mt][0] = *(uint2*)(sAlo + ar);
                alf[mt][1] = *(uint2*)(sAlo + ar + 8*STRH);
            }
            #pragma unroll
            for (int u = 0; u < 4; u++) {
                int br = (wn*32 + u*8 + g)*STRH + ko;
                bhf[u] = *(uint2*)(sBhi + br);
                blf[u] = *(uint2*)(sBlo + br);
            }
            #pragma unroll
            for (int mt = 0; mt < 4; mt++)
                #pragma unroll
                for (int u = 0; u < 4; u++) {
                    mma_f16(acc[mt][u], ahf[mt][0], ahf[mt][1], bhf[u]);
                    mma_f16(acc[mt][u], ahf[mt][0], ahf[mt][1], blf[u]);
                    mma_f16(acc[mt][u], alf[mt][0], alf[mt][1], bhf[u]);
                }
        }
    }
    __syncthreads();

    // partial overlay in smem (tiles are dead now)
    float* Mp = (float*)smem;           // [128][4]
    float* Lp = Mp + 512;
    int*   Ip = (int*)(Mp + 1024);

    const float NEG = -3.402823466e38f;
    #pragma unroll
    for (int mt = 0; mt < 4; mt++) {
        #pragma unroll
        for (int half = 0; half < 2; half++) {
            int row = wm*64 + mt*16 + g + half*8;
            float M = NEG, L = 0.f; int I = 0;
            #pragma unroll
            for (int u = 0; u < 4; u++) {
                #pragma unroll
                for (int j = 0; j < 2; j++) {
                    int col = wn*32 + u*8 + 2*t4 + j;
                    float s = 2.f*acc[mt][u][half*2 + j] - cbs_s[col];
                    if (s > M) { L = L*expf(M - s) + 1.f; M = s; I = col; }
                    else       { L += expf(s - M); }
                }
            }
            // reduce over the 4 t4-lanes (same g)
            #pragma unroll
            for (int off = 1; off <= 2; off <<= 1) {
                float m2 = __shfl_xor_sync(0xffffffffu, M, off);
                float l2 = __shfl_xor_sync(0xffffffffu, L, off);
                int   i2 = __shfl_xor_sync(0xffffffffu, I, off);
                float mn = fmaxf(M, m2);
                L = L*expf(M - mn) + l2*expf(m2 - mn);
                if (m2 > M || (m2 == M && i2 < I)) I = i2;
                M = mn;
            }
            if (t4 == 0) { Mp[row*4 + wn] = M; Lp[row*4 + wn] = L; Ip[row*4 + wn] = I; }
        }
    }
    __syncthreads();

    if (tid < 128) {
        float M = Mp[tid*4], L = Lp[tid*4]; int I = Ip[tid*4];
        #pragma unroll
        for (int n = 1; n < 4; n++) {
            float m2 = Mp[tid*4 + n], l2 = Lp[tid*4 + n];
            float mn = fmaxf(M, m2);
            L = L*expf(M - mn) + l2*expf(m2 - mn);
            if (m2 > M) I = Ip[tid*4 + n];   // ascending col blocks: ties keep first
            M = mn;
        }
        int pos = mtile*128 + tid;
        int slot = seg ? (172032 + q*32768 + pos) : (q*43008 + pos);
        g_hM[slot] = M; g_hL[slot] = L; g_hI[slot] = q*128 + I;
    }
}

// ======================= fuse =======================
__device__ __forceinline__ void merge4(int pos, int base, int stride, float& P, int& idx)
{
    float M = g_hM[base + pos], L = g_hL[base + pos]; int I = g_hI[base + pos];
    #pragma unroll
    for (int n = 1; n < 4; n++) {
        int s = base + n*stride + pos;
        float m2 = g_hM[s], l2 = g_hL[s];
        float mn = fmaxf(M, m2);
        L = L*expf(M - mn) + l2*expf(m2 - mn);
        if (m2 > M) I = g_hI[s];     // ascending quarters: ties keep first
        M = mn;
    }
    P = 1.f / L; idx = I;
}

__global__ void __launch_bounds__(256) fuse_kernel(
    const float* __restrict__ cbs, float* __restrict__ out)
{
    const float* cb0 = cbs;
    const float* cb1 = cbs + (size_t)KCB*CDIM;
    int x = threadIdx.x & 63;
    int y = blockIdx.x*4 + (threadIdx.x >> 6);
    int b = blockIdx.y;
    int pos0 = (b*64 + y)*64 + x;
    int pos1 = 32768 + (b*32 + (y>>1))*32 + (x>>1);
    int pos2 = 40960 + (b*16 + (y>>2))*16 + (x>>2);

    float pA, pB, pC; int zA, zB, zC;
    merge4(pos0, 0, 43008, pA, zA);
    merge4(pos1, 0, 43008, pB, zB);
    merge4(pos2, 0, 43008, pC, zC);
    int z1 = zA; float best = pA;
    if (pB > best) { best = pB; z1 = zB; }
    if (pC > best) { best = pC; z1 = zC; }
    float p2d; int z2;
    merge4(pos0, 172032, 32768, p2d, z2);

    out[OFF_Z + ((size_t)(b*2+0)*64 + y)*64 + x] = (float)z1;
    out[OFF_Z + ((size_t)(b*2+1)*64 + y)*64 + x] = (float)z2;

    const float4* r0 = (const float4*)(cb0 + (size_t)z1*CDIM);
    const float4* r1 = (const float4*)(cb1 + (size_t)z2*CDIM);
    size_t obase = (size_t)OFF_STE + (size_t)b*256*4096 + (size_t)y*64 + x;
    for (int c4 = 0; c4 < 64; c4++) {
        float4 a = r0[c4], qv = r1[c4];
        int c = c4*4;
        out[obase + (size_t)(c+0)*4096] = 0.5f*(a.x + qv.x);
        out[obase + (size_t)(c+1)*4096] = 0.5f*(a.y + qv.y);
        out[obase + (size_t)(c+2)*4096] = 0.5f*(a.z + qv.z);
        out[obase + (size_t)(c+3)*4096] = 0.5f*(a.w + qv.w);
    }
}

// ======================= launch =======================
extern "C" void kernel_launch(void* const* d_in, const int* in_sizes, int n_in,
                              void* d_out, int out_size)
{
    const float* image     = (const float*)d_in[0];  // (8,3,256,256)
    const float* conv_w    = (const float*)d_in[1];  // (256,3,4,4)
    const float* conv_b    = (const float*)d_in[2];  // (256,)
    const float* codebooks = (const float*)d_in[3];  // (4,512,256)
    float* out = (float*)d_out;

    cudaFuncSetAttribute(dist_mma_kernel, cudaFuncAttributeMaxDynamicSharedMemorySize, DSMEM);

    ds_kernel<<<1536, 256>>>(image, 0);
    ds_kernel<<<384, 256>>>(image, 1);
    cbsq_kernel<<<4, 256>>>(codebooks);

    conv_kernel<<<dim3(64, 8), 256>>>(image, conv_w, conv_b, 0);
    conv_kernel<<<dim3(32, 8), 256>>>(image, conv_w, conv_b, 1);
    conv_kernel<<<dim3(16, 8), 256>>>(image, conv_w, conv_b, 2);

    transpose_kernel<<<dim3(1024, 8), 256>>>(out);
    split_kernel<<<44032, 256>>>(codebooks);

    // cb0: 336 mtiles x 4 quarters = 1344 ; cb1: 256 x 4 = 1024
    dist_mma_kernel<<<2368, 256, DSMEM>>>();

    fuse_kernel<<<dim3(16, 8), 256>>>(codebooks, out);
}

// round 11
// speedup vs baseline: 2.6062x; 1.1624x over previous
#include <cuda_runtime.h>
#include <cuda_fp16.h>
#include <cstdint>

#define CDIM 256
#define KCB  512

static const int N_ENC0  = 8*256*64*64;        // 8388608
static const int OFF_Z   = N_ENC0;
static const int OFF_STE = N_ENC0 + 8*2*64*64; // + 65536

// ---- scratch (device globals; no allocation anywhere) ----
__device__ float g_img1[8*3*128*128];
__device__ float g_img2[8*3*64*64];
__device__ float g_enc0[8*64*64*256];   // NHWC scale0 (needed fp32 for output region 0)
__device__ float g_cbsq[2*KCB];         // ||cb||^2, 1024 rows
// fp16 hi/lo split operands, k-PERMUTED within each 16-chunk:
// j=k&15 -> slot = ((j&7)>>1)*4 + ((j>>3)<<1) + (j&1)   (lane t4 owns slots 4t4..4t4+3)
__device__ __half g_ehi[43008*256];     // concat enc0|enc1|enc2 rows
__device__ __half g_elo[43008*256];
__device__ __half g_cbhi[1024*256];     // cb0 rows 0..511, cb1 rows 512..1023
__device__ __half g_cblo[1024*256];
// per-(quarter, position) partials: cb0: q*43008 + pos ; cb1: 172032 + q*32768 + pos
__device__ float g_hM[303104];
__device__ float g_hL[303104];
__device__ int   g_hI[303104];

// m16n8k16 fp16 MMA, fp32 accum (sm_80+ PTX)
__device__ __forceinline__ void mma_f16(float* c, uint2 a01, uint2 a23, uint2 b) {
    asm volatile("mma.sync.aligned.m16n8k16.row.col.f32.f16.f16.f32 "
        "{%0,%1,%2,%3}, {%4,%5,%6,%7}, {%8,%9}, {%0,%1,%2,%3};"
        : "+f"(c[0]), "+f"(c[1]), "+f"(c[2]), "+f"(c[3])
        : "r"(a01.x), "r"(a23.x), "r"(a01.y), "r"(a23.y),
          "r"(b.x),  "r"(b.y));
}

__device__ __forceinline__ int permcol(int k) {
    int j = k & 15;
    return (k & ~15) + ((j & 7) >> 1)*4 + ((j >> 3) << 1) + (j & 1);
}

// ======================= small kernels =======================
__global__ void ds_kernel(const float* __restrict__ img, int sel)
{
    int Wout = sel ? 64 : 128;
    int f    = sel ? 4 : 2;
    int o    = sel ? 1 : 0;
    float* out = sel ? g_img2 : g_img1;
    int idx = blockIdx.x*blockDim.x + threadIdx.x;
    int total = 8*3*Wout*Wout;
    if (idx >= total) return;
    int x = idx % Wout, y = (idx / Wout) % Wout, bc = idx / (Wout*Wout);
    const float* p = img + (size_t)bc*256*256;
    int ry = y*f + o, rx = x*f + o;
    out[idx] = 0.25f*(p[ry*256+rx] + p[ry*256+rx+1] + p[(ry+1)*256+rx] + p[(ry+1)*256+rx+1]);
}

// codebook: squared norms + fp16 hi/lo split (k-permuted). grid 1024, block 256.
__global__ void __launch_bounds__(256) cbprep_kernel(const float* __restrict__ cbs)
{
    __shared__ float red[8];
    int r = blockIdx.x, k = threadIdx.x;
    float v = cbs[(size_t)r*256 + k];
    __half h = __float2half_rn(v);
    __half l = __float2half_rn(v - __half2float(h));
    size_t o = (size_t)r*256 + permcol(k);
    g_cbhi[o] = h; g_cblo[o] = l;
    // reduce v*v for cbsq
    float s = v*v;
    #pragma unroll
    for (int off = 16; off > 0; off >>= 1) s += __shfl_xor_sync(0xffffffffu, s, off);
    if ((k & 31) == 0) red[k >> 5] = s;
    __syncthreads();
    if (k == 0) {
        float t = 0.f;
        #pragma unroll
        for (int i = 0; i < 8; i++) t += red[i];
        g_cbsq[r] = t;
    }
}

// stride-4 4x4 conv, 3 in-ch -> 256 out-ch; writes fp16 split (+ fp32 NHWC for scale0)
// grid: (Hout, B); block: 256 threads (one per out channel).
__global__ void __launch_bounds__(256) conv_kernel(
    const float* __restrict__ ext_img, const float* __restrict__ w,
    const float* __restrict__ bias, int which)
{
    __shared__ float ins[12][256];
    int o = threadIdx.x;
    int y = blockIdx.x, b = blockIdx.y;
    int Hout = gridDim.x;
    int Win  = Hout * 4;

    const float* img = (which == 0) ? ext_img : (which == 1 ? g_img1 : g_img2);
    int rowbase = (which == 0) ? (b*64 + y)*64
                : (which == 1) ? 32768 + (b*32 + y)*32
                               : 40960 + (b*16 + y)*16;

    int tot = 12*Win;
    for (int i = o; i < tot; i += 256) {
        int x = i % Win; int r = i / Win;
        ins[r][x] = img[(((size_t)b*3 + (r>>2))*Win + 4*y + (r&3))*Win + x];
    }
    float wreg[48];
    #pragma unroll
    for (int j = 0; j < 48; j++) wreg[j] = w[(size_t)o*48 + j];
    float bo = bias[o];
    __syncthreads();

    int oc = permcol(o);
    for (int x = 0; x < Hout; x += 2) {
        // two independent sequential chains (same summation order as before per x)
        float accA = bo, accB = bo;
        #pragma unroll
        for (int j = 0; j < 48; j++) {
            int ic = j >> 4, ky = (j >> 2) & 3, kx = j & 3;
            accA += wreg[j] * ins[ic*4+ky][4*x+kx];
            accB += wreg[j] * ins[ic*4+ky][4*x+4+kx];
        }
        if (which == 0) {
            g_enc0[((size_t)rowbase + x)*256 + o] = accA;
            g_enc0[((size_t)rowbase + x + 1)*256 + o] = accB;
        }
        __half hA = __float2half_rn(accA);
        __half lA = __float2half_rn(accA - __half2float(hA));
        __half hB = __float2half_rn(accB);
        __half lB = __float2half_rn(accB - __half2float(hB));
        size_t oA = ((size_t)rowbase + x)*256 + oc;
        size_t oB = ((size_t)rowbase + x + 1)*256 + oc;
        g_ehi[oA] = hA; g_elo[oA] = lA;
        g_ehi[oB] = hB; g_elo[oB] = lB;
    }
}

// NHWC -> NCHW transpose for enc0 into output region 0
__global__ void __launch_bounds__(256) transpose_kernel(float* __restrict__ out)
{
    __shared__ float t[32][33];
    int tid = threadIdx.x;
    int p0 = blockIdx.x * 32;
    int c0 = blockIdx.y * 32;
    #pragma unroll
    for (int it = 0; it < 4; it++) {
        int r = (tid >> 5) + it*8, cc = tid & 31;
        t[r][cc] = g_enc0[(size_t)(p0 + r)*256 + c0 + cc];
    }
    __syncthreads();
    #pragma unroll
    for (int it = 0; it < 4; it++) {
        int r = (tid >> 5) + it*8, pc = tid & 31;
        int gp = p0 + pc;
        int b = gp >> 12, p = gp & 4095;
        out[((size_t)b*256 + c0 + r)*4096 + p] = t[pc][r];
    }
}

// ======================= fp16 mma.sync distance =======================
// CTA: M=128 positions x N=128 codes (quarter codebook), K=256 in 8 chunks of 32.
// dot ~= Ahi*Bhi + Ahi*Blo + Alo*Bhi (products exact in fp32 accum; dropped lo*lo ~2^-22).
// 8 warps: wm=w&1 (M 64), wn=w>>1 (N 32). Warp tile 64x32, 3 x m16n8k16 per (mt,u).
#define STRH 48                         // compact: 96B stride, conflict-free compute loads
#define TILEH (128*STRH)                // 6144 halves = 12288 B per operand
#define DSMEM (4*TILEH*2 + 512)        // 49664 bytes -> 2 CTAs/SM

__global__ void __launch_bounds__(256, 2) dist_mma_kernel()
{
    extern __shared__ char smem[];
    __half* sAhi = (__half*)smem;
    __half* sAlo = sAhi + TILEH;
    __half* sBhi = sAlo + TILEH;
    __half* sBlo = sBhi + TILEH;
    float*  cbs_s = (float*)(smem + 4*TILEH*2);   // 128 floats

    int tid = threadIdx.x;
    int lane = tid & 31, w = tid >> 5;
    int g = lane >> 2, t4 = lane & 3;
    int wm = w & 1, wn = w >> 1;

    int blk = blockIdx.x;
    int seg, mtile, q;
    if (blk < 1344) { seg = 0; mtile = blk >> 2; q = blk & 3; }
    else            { seg = 1; mtile = (blk - 1344) >> 2; q = (blk - 1344) & 3; }

    const __half* Ahi_g = g_ehi + (size_t)mtile*128*256;
    const __half* Alo_g = g_elo + (size_t)mtile*128*256;
    int cbrow = (seg ? 512 : 0) + q*128;
    const __half* Bhi_g = g_cbhi + (size_t)cbrow*256;
    const __half* Blo_g = g_cblo + (size_t)cbrow*256;

    if (tid < 128) cbs_s[tid] = g_cbsq[cbrow + tid];

    float acc[4][4][4];
    #pragma unroll
    for (int mt = 0; mt < 4; mt++)
        #pragma unroll
        for (int u = 0; u < 4; u++)
            #pragma unroll
            for (int e = 0; e < 4; e++) acc[mt][u][e] = 0.f;

    const __half* gsrc[4] = {Ahi_g, Alo_g, Bhi_g, Blo_g};
    __half* sdst[4] = {sAhi, sAlo, sBhi, sBlo};

    for (int kc = 0; kc < 8; kc++) {
        if (kc > 0) __syncthreads();
        #pragma unroll
        for (int op = 0; op < 4; op++) {
            #pragma unroll
            for (int it = 0; it < 2; it++) {
                int c = it*256 + tid;
                int r = c >> 2, sgs = c & 3;
                *(uint4*)(sdst[op] + r*STRH + sgs*8) =
                    *(const uint4*)(gsrc[op] + (size_t)r*256 + kc*32 + sgs*8);
            }
        }
        __syncthreads();

        #pragma unroll
        for (int s = 0; s < 2; s++) {
            int ko = s*16 + t4*4;
            uint2 bhf[4], blf[4];
            #pragma unroll
            for (int u = 0; u < 4; u++) {
                int br = (wn*32 + u*8 + g)*STRH + ko;
                bhf[u] = *(uint2*)(sBhi + br);
                blf[u] = *(uint2*)(sBlo + br);
            }
            #pragma unroll
            for (int mt = 0; mt < 4; mt++) {
                int ar = (wm*64 + mt*16 + g)*STRH + ko;
                uint2 ah0 = *(uint2*)(sAhi + ar);
                uint2 ah1 = *(uint2*)(sAhi + ar + 8*STRH);
                uint2 al0 = *(uint2*)(sAlo + ar);
                uint2 al1 = *(uint2*)(sAlo + ar + 8*STRH);
                #pragma unroll
                for (int u = 0; u < 4; u++) {
                    mma_f16(acc[mt][u], ah0, ah1, bhf[u]);
                    mma_f16(acc[mt][u], ah0, ah1, blf[u]);
                    mma_f16(acc[mt][u], al0, al1, bhf[u]);
                }
            }
        }
    }
    __syncthreads();

    // partial overlay in smem (tiles dead now)
    float* Mp = (float*)smem;           // [128][4]
    float* Lp = Mp + 512;
    int*   Ip = (int*)(Mp + 1024);

    const float NEG = -3.402823466e38f;
    #pragma unroll
    for (int mt = 0; mt < 4; mt++) {
        #pragma unroll
        for (int half = 0; half < 2; half++) {
            int row = wm*64 + mt*16 + g + half*8;
            float M = NEG, L = 0.f; int I = 0;
            #pragma unroll
            for (int u = 0; u < 4; u++) {
                #pragma unroll
                for (int j = 0; j < 2; j++) {
                    int col = wn*32 + u*8 + 2*t4 + j;
                    float s = 2.f*acc[mt][u][half*2 + j] - cbs_s[col];
                    if (s > M) { L = L*expf(M - s) + 1.f; M = s; I = col; }
                    else       { L += expf(s - M); }
                }
            }
            #pragma unroll
            for (int off = 1; off <= 2; off <<= 1) {
                float m2 = __shfl_xor_sync(0xffffffffu, M, off);
                float l2 = __shfl_xor_sync(0xffffffffu, L, off);
                int   i2 = __shfl_xor_sync(0xffffffffu, I, off);
                float mn = fmaxf(M, m2);
                L = L*expf(M - mn) + l2*expf(m2 - mn);
                if (m2 > M || (m2 == M && i2 < I)) I = i2;
                M = mn;
            }
            if (t4 == 0) { Mp[row*4 + wn] = M; Lp[row*4 + wn] = L; Ip[row*4 + wn] = I; }
        }
    }
    __syncthreads();

    if (tid < 128) {
        float M = Mp[tid*4], L = Lp[tid*4]; int I = Ip[tid*4];
        #pragma unroll
        for (int n = 1; n < 4; n++) {
            float m2 = Mp[tid*4 + n], l2 = Lp[tid*4 + n];
            float mn = fmaxf(M, m2);
            L = L*expf(M - mn) + l2*expf(m2 - mn);
            if (m2 > M) I = Ip[tid*4 + n];   // ascending col blocks: ties keep first
            M = mn;
        }
        int pos = mtile*128 + tid;
        int slot = seg ? (172032 + q*32768 + pos) : (q*43008 + pos);
        g_hM[slot] = M; g_hL[slot] = L; g_hI[slot] = q*128 + I;
    }
}

// ======================= fuse =======================
__device__ __forceinline__ void merge4(int pos, int base, int stride, float& P, int& idx)
{
    float M = g_hM[base + pos], L = g_hL[base + pos]; int I = g_hI[base + pos];
    #pragma unroll
    for (int n = 1; n < 4; n++) {
        int s = base + n*stride + pos;
        float m2 = g_hM[s], l2 = g_hL[s];
        float mn = fmaxf(M, m2);
        L = L*expf(M - mn) + l2*expf(m2 - mn);
        if (m2 > M) I = g_hI[s];     // ascending quarters: ties keep first
        M = mn;
    }
    P = 1.f / L; idx = I;
}

__global__ void __launch_bounds__(256) fuse_kernel(
    const float* __restrict__ cbs, float* __restrict__ out)
{
    const float* cb0 = cbs;
    const float* cb1 = cbs + (size_t)KCB*CDIM;
    int x = threadIdx.x & 63;
    int y = blockIdx.x*4 + (threadIdx.x >> 6);
    int b = blockIdx.y;
    int pos0 = (b*64 + y)*64 + x;
    int pos1 = 32768 + (b*32 + (y>>1))*32 + (x>>1);
    int pos2 = 40960 + (b*16 + (y>>2))*16 + (x>>2);

    float pA, pB, pC; int zA, zB, zC;
    merge4(pos0, 0, 43008, pA, zA);
    merge4(pos1, 0, 43008, pB, zB);
    merge4(pos2, 0, 43008, pC, zC);
    int z1 = zA; float best = pA;
    if (pB > best) { best = pB; z1 = zB; }
    if (pC > best) { best = pC; z1 = zC; }
    float p2d; int z2;
    merge4(pos0, 172032, 32768, p2d, z2);

    out[OFF_Z + ((size_t)(b*2+0)*64 + y)*64 + x] = (float)z1;
    out[OFF_Z + ((size_t)(b*2+1)*64 + y)*64 + x] = (float)z2;

    const float4* r0 = (const float4*)(cb0 + (size_t)z1*CDIM);
    const float4* r1 = (const float4*)(cb1 + (size_t)z2*CDIM);
    size_t obase = (size_t)OFF_STE + (size_t)b*256*4096 + (size_t)y*64 + x;
    for (int c4 = 0; c4 < 64; c4++) {
        float4 a = r0[c4], qv = r1[c4];
        int c = c4*4;
        out[obase + (size_t)(c+0)*4096] = 0.5f*(a.x + qv.x);
        out[obase + (size_t)(c+1)*4096] = 0.5f*(a.y + qv.y);
        out[obase + (size_t)(c+2)*4096] = 0.5f*(a.z + qv.z);
        out[obase + (size_t)(c+3)*4096] = 0.5f*(a.w + qv.w);
    }
}

// ======================= launch =======================
extern "C" void kernel_launch(void* const* d_in, const int* in_sizes, int n_in,
                              void* d_out, int out_size)
{
    const float* image     = (const float*)d_in[0];  // (8,3,256,256)
    const float* conv_w    = (const float*)d_in[1];  // (256,3,4,4)
    const float* conv_b    = (const float*)d_in[2];  // (256,)
    const float* codebooks = (const float*)d_in[3];  // (4,512,256)
    float* out = (float*)d_out;

    cudaFuncSetAttribute(dist_mma_kernel, cudaFuncAttributeMaxDynamicSharedMemorySize, DSMEM);

    ds_kernel<<<1536, 256>>>(image, 0);
    ds_kernel<<<384, 256>>>(image, 1);
    cbprep_kernel<<<1024, 256>>>(codebooks);

    conv_kernel<<<dim3(64, 8), 256>>>(image, conv_w, conv_b, 0);
    conv_kernel<<<dim3(32, 8), 256>>>(image, conv_w, conv_b, 1);
    conv_kernel<<<dim3(16, 8), 256>>>(image, conv_w, conv_b, 2);

    transpose_kernel<<<dim3(1024, 8), 256>>>(out);

    // cb0: 336 mtiles x 4 quarters = 1344 ; cb1: 256 x 4 = 1024
    dist_mma_kernel<<<2368, 256, DSMEM>>>();

    fuse_kernel<<<dim3(16, 8), 256>>>(codebooks, out);
}